// round 16
// baseline (speedup 1.0000x reference)
#include <cuda_runtime.h>
#include <cstdint>
#include <cstddef>

// ---------------------------------------------------------------------------
// 2-layer LSTM (T=512, B=4096, D=64, H=70) + MLP head.
// R15: rec = R11 GEMM shape, but gx prefetch moved from registers to a
//      cp.async-staged SMEM buffer (frees ~25 regs at the 128-reg ceiling,
//      cuts per-step issue). gemm_x/head = R14 (best).
// ---------------------------------------------------------------------------

#define TT   512
#define BB   4096
#define DD   64
#define HH   70
#define GP   288          // padded gate cols (4*72), col = 4n + gate
#define GTHR 512          // gemm_x threads (16 warps)
#define NPERS 148         // persistent gemm CTAs
#define RTHR 512          // recurrence threads (16 warps)
#define RBLK 128          // recurrence CTAs, 32 rows each

typedef unsigned long long u64;

// scratch: gate-x buffer [T][288][B] (reused for both layers),
//          h0 sequence [T][70][B], final h1 [70][B]
__device__ float g_gx[(size_t)TT * GP * BB];
__device__ float g_h0[(size_t)TT * HH * BB];
__device__ float g_h1[HH * BB];

#define FMA2A(d, a, b) \
    asm("fma.rn.f32x2 %0, %1, %2, %0;" : "+l"(d) : "l"(a), "l"(b))

#define CP16(dst_u32, src) \
    asm volatile("cp.async.ca.shared.global [%0], [%1], 16;" \
                 :: "r"(dst_u32), "l"(src))
#define CP_COMMIT() asm volatile("cp.async.commit_group;")
#define CP_WAIT0()  asm volatile("cp.async.wait_group 0;")
#define CP_WAIT1()  asm volatile("cp.async.wait_group 1;")

__device__ __forceinline__ u64 dup2(float v) {
    u64 r;
    unsigned int u = __float_as_uint(v);
    asm("mov.b64 %0, {%1,%2};" : "=l"(r) : "r"(u), "r"(u));
    return r;
}
__device__ __forceinline__ void unpack2f(u64 v, float& lo, float& hi) {
    unsigned int a, b;
    asm("mov.b64 {%0,%1}, %2;" : "=r"(a), "=r"(b) : "l"(v));
    lo = __uint_as_float(a);
    hi = __uint_as_float(b);
}

__device__ __forceinline__ float sigm(float x) {
    return __fdividef(1.f, 1.f + __expf(-x));
}
__device__ __forceinline__ float tanh_(float x) {
    return __fdividef(2.f, 1.f + __expf(-2.f * x)) - 1.f;
}

// gate-major row j -> interleaved column
__device__ __forceinline__ int gcol(int j) {
    int g = j / HH, n = j - g * HH;
    return 4 * n + g;
}

__device__ __forceinline__ uint32_t smem_u32(const void* p) {
    return (uint32_t)__cvta_generic_to_shared(p);
}

// ---------------------------------------------------------------------------
// gx = X @ W^T + (b1 + b2), output layout [T][GP][B].   (R14, unchanged)
// 16 warps: warp w = cols [18w,18w+18), lane = rows {lane+32g, g<4}.
// ---------------------------------------------------------------------------
template <int KK, bool XTB>
__global__ void __launch_bounds__(GTHR, 1)
gemm_x(const float* __restrict__ X, const float* __restrict__ W,
       const float* __restrict__ b1, const float* __restrict__ b2,
       float* __restrict__ gx)
{
    constexpr int XS_ELEMS = XTB ? (128 * 68) : (KK * 128);

    extern __shared__ float sm[];
    float* Wt   = sm;                 // [KK][GP]
    float* bias = Wt + KK * GP;       // [GP]
    float* xsA  = bias + GP;
    float* xsB  = xsA + XS_ELEMS;

    const int tid  = threadIdx.x;
    const int lane = tid & 31;
    const int w    = tid >> 5;        // 0..15

    for (int i = tid; i < (KK + 1) * GP; i += GTHR) sm[i] = 0.f;
    __syncthreads();
    for (int idx = tid; idx < 4 * HH * KK; idx += GTHR) {
        int j = idx / KK, k = idx - j * KK;
        Wt[k * GP + gcol(j)] = W[idx];
    }
    for (int j = tid; j < 4 * HH; j += GTHR)
        bias[gcol(j)] = b1[j] + b2[j];
    __syncthreads();

    const u64* bp = reinterpret_cast<const u64*>(bias + 18 * w);

    const int ntiles = (TT * BB) / 128;   // 16384

    auto stage = [&](int tile, float* buf) {
        const int m0 = tile * 128;
        const int t  = m0 >> 12;
        const int b0 = m0 & 4095;
        if (XTB) {
#pragma unroll
            for (int ii = 0; ii < (128 * 16) / GTHR; ii++) {
                int idx = tid + ii * GTHR;
                int r = idx >> 4, c = idx & 15;
                int cs = c ^ ((r >> 3) & 3);
                const float* src = X + ((size_t)t * BB + b0 + r) * KK + c * 4;
                CP16(smem_u32(buf + r * 68 + cs * 4), src);
            }
        } else {
#pragma unroll
            for (int ii = 0; ii < (KK * 32 + GTHR - 1) / GTHR; ii++) {
                int idx = tid + ii * GTHR;
                if (idx < KK * 32) {
                    int k = idx >> 5, c = idx & 31;
                    const float* src = X + ((size_t)t * KK + k) * BB + b0 + c * 4;
                    CP16(smem_u32(buf + k * 128 + c * 4), src);
                }
            }
        }
        CP_COMMIT();
    };

    int myfirst = blockIdx.x;
    if (myfirst < ntiles) stage(myfirst, xsA);

    int bufsel = 0;
    for (int tile = myfirst; tile < ntiles; tile += gridDim.x) {
        float* cur = bufsel ? xsB : xsA;
        float* nxt = bufsel ? xsA : xsB;

        __syncthreads();
        bool hasnext = (tile + gridDim.x) < ntiles;
        if (hasnext) { stage(tile + gridDim.x, nxt); CP_WAIT1(); }
        else         { CP_WAIT0(); }
        __syncthreads();

        const int m0 = tile * 128;
        const int t  = m0 >> 12;
        const int b0 = m0 & 4095;

        u64 a[4][9];
#pragma unroll
        for (int j = 0; j < 9; j++) {
            u64 bv = bp[j];
#pragma unroll
            for (int g = 0; g < 4; g++) a[g][j] = bv;
        }

        if (XTB) {
            const int xorp = (lane >> 3) & 3;
#pragma unroll 1
            for (int k = 0; k < KK; k++) {
                int sw = (((k >> 2) ^ xorp) << 2) + (k & 3);
                u64 xq[4];
#pragma unroll
                for (int g = 0; g < 4; g++)
                    xq[g] = dup2(cur[(lane + 32 * g) * 68 + sw]);
                const u64* Wk =
                    reinterpret_cast<const u64*>(Wt + k * GP + 18 * w);
#pragma unroll
                for (int j = 0; j < 9; j++) {
                    u64 w2 = Wk[j];
#pragma unroll
                    for (int g = 0; g < 4; g++)
                        FMA2A(a[g][j], w2, xq[g]);
                }
            }
        } else {
#pragma unroll 1
            for (int k = 0; k < KK; k++) {
                u64 xq[4];
#pragma unroll
                for (int g = 0; g < 4; g++)
                    xq[g] = dup2(cur[k * 128 + lane + 32 * g]);
                const u64* Wk =
                    reinterpret_cast<const u64*>(Wt + k * GP + 18 * w);
#pragma unroll
                for (int j = 0; j < 9; j++) {
                    u64 w2 = Wk[j];
#pragma unroll
                    for (int g = 0; g < 4; g++)
                        FMA2A(a[g][j], w2, xq[g]);
                }
            }
        }

        float* gbase = gx + (size_t)t * GP * BB + b0;
#pragma unroll
        for (int g = 0; g < 4; g++) {
            int ro = lane + 32 * g;
#pragma unroll
            for (int j = 0; j < 9; j++) {
                int c0 = 18 * w + 2 * j;
                float lo, hi;
                unpack2f(a[g][j], lo, hi);
                gbase[(size_t)c0 * BB + ro]       = lo;
                gbase[(size_t)(c0 + 1) * BB + ro] = hi;
            }
        }
        bufsel ^= 1;
    }
}

// ---------------------------------------------------------------------------
// Recurrence: R11 split-k GEMM shape; gx staged to SMEM via cp.async
// (issued at step start, consumed after the post-GEMM barrier).
// ---------------------------------------------------------------------------
#define UPD_ITERS ((HH * 32 + RTHR - 1) / RTHR)   // 5
#define GX_CHUNKS (4 * HH * 8)                    // 2240 CP16 per step

template <bool WRITE_SEQ>
__global__ void __launch_bounds__(RTHR, 1)
lstm_rec(const float* __restrict__ gx, const float* __restrict__ Whh,
         float* __restrict__ seq_out, float* __restrict__ fin_out)
{
    extern __shared__ float sm[];
    float* Ws  = sm;                  // [HH][GP]   weights, col = gcol(j)
    float* hb  = Ws + HH * GP;        // [HH][32]   h state
    float* gbA = hb + HH * 32;        // [GP][33]   gate spill, k-half 0
    float* gbB = gbA + GP * 33;       // [GP][33]   gate spill, k-half 1
    float* gxs = gbB + GP * 33;       // [GP][32]   staged gx(t)

    const int tid  = threadIdx.x;
    const int lane = tid & 31;
    const int w    = tid >> 5;          // 0..15
    const int wr   = w & 7;             // row-quad index
    const int kh   = w >> 3;            // k-half
    const int row0 = blockIdx.x * 32;

    for (int i = tid; i < HH * GP; i += RTHR) Ws[i] = 0.f;
    for (int i = tid; i < HH * 32; i += RTHR) hb[i] = 0.f;
    __syncthreads();

    for (int idx = tid; idx < 4 * HH * HH; idx += RTHR) {
        int j = idx / HH, k = idx - j * HH;
        Ws[k * GP + gcol(j)] = Whh[idx];
    }
    __syncthreads();

    float creg[UPD_ITERS];
#pragma unroll
    for (int i = 0; i < UPD_ITERS; i++) creg[i] = 0.f;

    // GEMM bases for this warp's k-half
    const float* Wl0 = Ws + lane + (kh ? 35 * GP : 0);
    const float* hr0 = hb + 4 * wr + (kh ? 35 * 32 : 0);
    float* gb = kh ? gbB : gbA;

    for (int t = 0; t < TT; t++) {
        // ---- stage gx(t) into SMEM via cp.async (hides under GEMM)
        {
            const float* gxt = gx + (size_t)t * GP * BB + row0;
#pragma unroll
            for (int i = 0; i < (GX_CHUNKS + RTHR - 1) / RTHR; i++) {
                int idx = tid + i * RTHR;
                if (idx < GX_CHUNKS) {
                    int col = idx >> 3, ch = idx & 7;
                    CP16(smem_u32(gxs + col * 32 + ch * 4),
                         gxt + (size_t)col * BB + ch * 4);
                }
            }
            CP_COMMIT();
        }

        // ---- GEMM (35 k-iters): acc[2j+p] = row pair of col lane+32j
        u64 acc[18];
#pragma unroll
        for (int q = 0; q < 18; q++) acc[q] = 0ull;

#pragma unroll 5
        for (int k = 0; k < 35; k++) {
            ulonglong2 h2 =
                *reinterpret_cast<const ulonglong2*>(hr0 + k * 32);
            const float* Wk = Wl0 + k * GP;
#pragma unroll
            for (int j = 0; j < 9; j++) {
                u64 w2 = dup2(Wk[32 * j]);
                FMA2A(acc[2 * j],     w2, h2.x);
                FMA2A(acc[2 * j + 1], w2, h2.y);
            }
        }

        // ---- spill gates: gb[c][4wr+u], c = lane + 32j
#pragma unroll
        for (int j = 0; j < 9; j++) {
            int c = lane + 32 * j;
            float v0, v1, v2, v3;
            unpack2f(acc[2 * j],     v0, v1);
            unpack2f(acc[2 * j + 1], v2, v3);
            gb[c * 33 + 4 * wr + 0] = v0;
            gb[c * 33 + 4 * wr + 1] = v1;
            gb[c * 33 + 4 * wr + 2] = v2;
            gb[c * 33 + 4 * wr + 3] = v3;
        }
        CP_WAIT0();        // own gx chunks landed (long since, under GEMM)
        __syncthreads();   // publishes spills + staged gx to all threads

        // ---- cell update: flat over (unit, row); reads gx from SMEM
#pragma unroll
        for (int i = 0; i < UPD_ITERS; i++) {
            int idx = tid + i * RTHR;
            if (idx < HH * 32) {
                int n = idx >> 5, r = idx & 31;
                float gi = gbA[(4 * n + 0) * 33 + r] + gbB[(4 * n + 0) * 33 + r]
                         + gxs[(4 * n + 0) * 32 + r];
                float gf = gbA[(4 * n + 1) * 33 + r] + gbB[(4 * n + 1) * 33 + r]
                         + gxs[(4 * n + 1) * 32 + r];
                float gg = gbA[(4 * n + 2) * 33 + r] + gbB[(4 * n + 2) * 33 + r]
                         + gxs[(4 * n + 2) * 32 + r];
                float go = gbA[(4 * n + 3) * 33 + r] + gbB[(4 * n + 3) * 33 + r]
                         + gxs[(4 * n + 3) * 32 + r];
                float iv = sigm(gi);
                float fv = sigm(gf);
                float gv = tanh_(gg);
                float ov = sigm(go);
                float c = __fmaf_rn(fv, creg[i], iv * gv);
                creg[i] = c;
                float h = ov * tanh_(c);
                hb[n * 32 + r] = h;
                if (WRITE_SEQ)
                    seq_out[((size_t)t * HH + n) * BB + row0 + r] = h;
                if (!WRITE_SEQ && t == TT - 1)
                    fin_out[(size_t)n * BB + row0 + r] = h;
            }
        }
        __syncthreads();   // hb(t) ready, gb/gxs consumed, before next step
    }
}

// head: out = sigmoid(relu(h1 @ W1.T + b1) @ W2.T + b2)
__global__ void __launch_bounds__(256)
head_kernel(const float* __restrict__ h1,
            const float* __restrict__ W1, const float* __restrict__ b1,
            const float* __restrict__ W2, const float* __restrict__ b2,
            float* __restrict__ out)
{
    __shared__ float sW1[50 * HH];
    __shared__ float sb1[50];
    __shared__ float sW2[50];
    __shared__ float sb2;
    for (int i = threadIdx.x; i < 50 * HH; i += 256) sW1[i] = W1[i];
    if (threadIdx.x < 50) {
        sb1[threadIdx.x] = b1[threadIdx.x];
        sW2[threadIdx.x] = W2[threadIdx.x];
    }
    if (threadIdx.x == 0) sb2 = b2[0];
    __syncthreads();

    int row = blockIdx.x * 256 + threadIdx.x;
    float h[HH];
#pragma unroll
    for (int n = 0; n < HH; n++) h[n] = h1[n * BB + row];

    float o = sb2;
    for (int s = 0; s < 50; s++) {
        float a = sb1[s];
#pragma unroll
        for (int n = 0; n < HH; n++) a += h[n] * sW1[s * HH + n];
        a = fmaxf(a, 0.f);
        o += a * sW2[s];
    }
    out[row] = sigm(o);
}

extern "C" void kernel_launch(void* const* d_in, const int* in_sizes, int n_in,
                              void* d_out, int out_size)
{
    int o = (n_in >= 14 && in_sizes[1] == 1) ? 2 : 1;
    const float* data_in = (const float*)d_in[0];
    const float* W_ih0 = (const float*)d_in[o + 0];
    const float* W_hh0 = (const float*)d_in[o + 1];
    const float* b_ih0 = (const float*)d_in[o + 2];
    const float* b_hh0 = (const float*)d_in[o + 3];
    const float* W_ih1 = (const float*)d_in[o + 4];
    const float* W_hh1 = (const float*)d_in[o + 5];
    const float* b_ih1 = (const float*)d_in[o + 6];
    const float* b_hh1 = (const float*)d_in[o + 7];
    const float* W1    = (const float*)d_in[o + 8];
    const float* b1    = (const float*)d_in[o + 9];
    const float* W2    = (const float*)d_in[o + 10];
    const float* b2    = (const float*)d_in[o + 11];

    float *gxp = nullptr, *h0p = nullptr, *h1p = nullptr;
    cudaGetSymbolAddress((void**)&gxp, g_gx);
    cudaGetSymbolAddress((void**)&h0p, g_h0);
    cudaGetSymbolAddress((void**)&h1p, g_h1);

    const int smx0 = ((DD + 1) * GP) * 4 + 2 * (128 * 68) * 4;         // ~145 KB
    const int smx1 = ((HH + 1) * GP) * 4 + 2 * (HH * 128) * 4;         // ~154 KB
    const int smr  = (HH * GP + HH * 32 + 2 * GP * 33 + GP * 32) * 4;  // ~198 KB

    cudaFuncSetAttribute((const void*)gemm_x<DD, true>,
                         cudaFuncAttributeMaxDynamicSharedMemorySize, smx0);
    cudaFuncSetAttribute((const void*)gemm_x<HH, false>,
                         cudaFuncAttributeMaxDynamicSharedMemorySize, smx1);
    cudaFuncSetAttribute((const void*)lstm_rec<true>,
                         cudaFuncAttributeMaxDynamicSharedMemorySize, smr);
    cudaFuncSetAttribute((const void*)lstm_rec<false>,
                         cudaFuncAttributeMaxDynamicSharedMemorySize, smr);

    gemm_x<DD, true><<<NPERS, GTHR, smx0>>>(data_in, W_ih0, b_ih0, b_hh0, gxp);
    lstm_rec<true><<<RBLK, RTHR, smr>>>(gxp, W_hh0, h0p, nullptr);
    gemm_x<HH, false><<<NPERS, GTHR, smx1>>>(h0p, W_ih1, b_ih1, b_hh1, gxp);
    lstm_rec<false><<<RBLK, RTHR, smr>>>(gxp, W_hh1, nullptr, h1p);
    head_kernel<<<BB / 256, 256>>>(h1p, W1, b1, W2, b2, (float*)d_out);
}

// round 17
// speedup vs baseline: 1.0755x; 1.0755x over previous
#include <cuda_runtime.h>
#include <cstdint>
#include <cstddef>

// ---------------------------------------------------------------------------
// 2-layer LSTM (T=512, B=4096, D=64, H=70) + MLP head.
// R16: rec reverted to R14 (register gx prefetch, best 2.687 ms/layer).
//      gemm_x = R14 shape with k-loop unroll 1 -> 2 (cross-iteration load
//      hoisting to close the 1.44x latency gap vs FMA floor).
// ---------------------------------------------------------------------------

#define TT   512
#define BB   4096
#define DD   64
#define HH   70
#define GP   288          // padded gate cols (4*72), col = 4n + gate
#define GTHR 512          // gemm_x threads (16 warps)
#define NPERS 148         // persistent gemm CTAs
#define RTHR 512          // recurrence threads (16 warps)
#define RBLK 128          // recurrence CTAs, 32 rows each

typedef unsigned long long u64;

// scratch: gate-x buffer [T][288][B] (reused for both layers),
//          h0 sequence [T][70][B], final h1 [70][B]
__device__ float g_gx[(size_t)TT * GP * BB];
__device__ float g_h0[(size_t)TT * HH * BB];
__device__ float g_h1[HH * BB];

#define FMA2A(d, a, b) \
    asm("fma.rn.f32x2 %0, %1, %2, %0;" : "+l"(d) : "l"(a), "l"(b))

#define CP16(dst_u32, src) \
    asm volatile("cp.async.ca.shared.global [%0], [%1], 16;" \
                 :: "r"(dst_u32), "l"(src))
#define CP_COMMIT() asm volatile("cp.async.commit_group;")
#define CP_WAIT0()  asm volatile("cp.async.wait_group 0;")
#define CP_WAIT1()  asm volatile("cp.async.wait_group 1;")

__device__ __forceinline__ u64 dup2(float v) {
    u64 r;
    unsigned int u = __float_as_uint(v);
    asm("mov.b64 %0, {%1,%2};" : "=l"(r) : "r"(u), "r"(u));
    return r;
}
__device__ __forceinline__ void unpack2f(u64 v, float& lo, float& hi) {
    unsigned int a, b;
    asm("mov.b64 {%0,%1}, %2;" : "=r"(a), "=r"(b) : "l"(v));
    lo = __uint_as_float(a);
    hi = __uint_as_float(b);
}

__device__ __forceinline__ float sigm(float x) {
    return __fdividef(1.f, 1.f + __expf(-x));
}
__device__ __forceinline__ float tanh_(float x) {
    return __fdividef(2.f, 1.f + __expf(-2.f * x)) - 1.f;
}

// gate-major row j -> interleaved column
__device__ __forceinline__ int gcol(int j) {
    int g = j / HH, n = j - g * HH;
    return 4 * n + g;
}

__device__ __forceinline__ uint32_t smem_u32(const void* p) {
    return (uint32_t)__cvta_generic_to_shared(p);
}

// ---------------------------------------------------------------------------
// gx = X @ W^T + (b1 + b2), output layout [T][GP][B].
// 16 warps: warp w = cols [18w,18w+18), lane = rows {lane+32g, g<4}.
// k-loop unroll 2 (the single change vs R14).
// ---------------------------------------------------------------------------
template <int KK, bool XTB>
__global__ void __launch_bounds__(GTHR, 1)
gemm_x(const float* __restrict__ X, const float* __restrict__ W,
       const float* __restrict__ b1, const float* __restrict__ b2,
       float* __restrict__ gx)
{
    constexpr int XS_ELEMS = XTB ? (128 * 68) : (KK * 128);

    extern __shared__ float sm[];
    float* Wt   = sm;                 // [KK][GP]
    float* bias = Wt + KK * GP;       // [GP]
    float* xsA  = bias + GP;
    float* xsB  = xsA + XS_ELEMS;

    const int tid  = threadIdx.x;
    const int lane = tid & 31;
    const int w    = tid >> 5;        // 0..15

    for (int i = tid; i < (KK + 1) * GP; i += GTHR) sm[i] = 0.f;
    __syncthreads();
    for (int idx = tid; idx < 4 * HH * KK; idx += GTHR) {
        int j = idx / KK, k = idx - j * KK;
        Wt[k * GP + gcol(j)] = W[idx];
    }
    for (int j = tid; j < 4 * HH; j += GTHR)
        bias[gcol(j)] = b1[j] + b2[j];
    __syncthreads();

    const u64* bp = reinterpret_cast<const u64*>(bias + 18 * w);

    const int ntiles = (TT * BB) / 128;   // 16384

    auto stage = [&](int tile, float* buf) {
        const int m0 = tile * 128;
        const int t  = m0 >> 12;
        const int b0 = m0 & 4095;
        if (XTB) {
#pragma unroll
            for (int ii = 0; ii < (128 * 16) / GTHR; ii++) {
                int idx = tid + ii * GTHR;
                int r = idx >> 4, c = idx & 15;
                int cs = c ^ ((r >> 3) & 3);
                const float* src = X + ((size_t)t * BB + b0 + r) * KK + c * 4;
                CP16(smem_u32(buf + r * 68 + cs * 4), src);
            }
        } else {
#pragma unroll
            for (int ii = 0; ii < (KK * 32 + GTHR - 1) / GTHR; ii++) {
                int idx = tid + ii * GTHR;
                if (idx < KK * 32) {
                    int k = idx >> 5, c = idx & 31;
                    const float* src = X + ((size_t)t * KK + k) * BB + b0 + c * 4;
                    CP16(smem_u32(buf + k * 128 + c * 4), src);
                }
            }
        }
        CP_COMMIT();
    };

    int myfirst = blockIdx.x;
    if (myfirst < ntiles) stage(myfirst, xsA);

    int bufsel = 0;
    for (int tile = myfirst; tile < ntiles; tile += gridDim.x) {
        float* cur = bufsel ? xsB : xsA;
        float* nxt = bufsel ? xsA : xsB;

        __syncthreads();
        bool hasnext = (tile + gridDim.x) < ntiles;
        if (hasnext) { stage(tile + gridDim.x, nxt); CP_WAIT1(); }
        else         { CP_WAIT0(); }
        __syncthreads();

        const int m0 = tile * 128;
        const int t  = m0 >> 12;
        const int b0 = m0 & 4095;

        u64 a[4][9];
#pragma unroll
        for (int j = 0; j < 9; j++) {
            u64 bv = bp[j];
#pragma unroll
            for (int g = 0; g < 4; g++) a[g][j] = bv;
        }

        if (XTB) {
            const int xorp = (lane >> 3) & 3;
#pragma unroll 2
            for (int k = 0; k < KK; k++) {
                int sw = (((k >> 2) ^ xorp) << 2) + (k & 3);
                u64 xq[4];
#pragma unroll
                for (int g = 0; g < 4; g++)
                    xq[g] = dup2(cur[(lane + 32 * g) * 68 + sw]);
                const u64* Wk =
                    reinterpret_cast<const u64*>(Wt + k * GP + 18 * w);
#pragma unroll
                for (int j = 0; j < 9; j++) {
                    u64 w2 = Wk[j];
#pragma unroll
                    for (int g = 0; g < 4; g++)
                        FMA2A(a[g][j], w2, xq[g]);
                }
            }
        } else {
#pragma unroll 2
            for (int k = 0; k < KK; k++) {
                u64 xq[4];
#pragma unroll
                for (int g = 0; g < 4; g++)
                    xq[g] = dup2(cur[k * 128 + lane + 32 * g]);
                const u64* Wk =
                    reinterpret_cast<const u64*>(Wt + k * GP + 18 * w);
#pragma unroll
                for (int j = 0; j < 9; j++) {
                    u64 w2 = Wk[j];
#pragma unroll
                    for (int g = 0; g < 4; g++)
                        FMA2A(a[g][j], w2, xq[g]);
                }
            }
        }

        float* gbase = gx + (size_t)t * GP * BB + b0;
#pragma unroll
        for (int g = 0; g < 4; g++) {
            int ro = lane + 32 * g;
#pragma unroll
            for (int j = 0; j < 9; j++) {
                int c0 = 18 * w + 2 * j;
                float lo, hi;
                unpack2f(a[g][j], lo, hi);
                gbase[(size_t)c0 * BB + ro]       = lo;
                gbase[(size_t)(c0 + 1) * BB + ro] = hi;
            }
        }
        bufsel ^= 1;
    }
}

// ---------------------------------------------------------------------------
// Recurrence (R14/R11, unchanged — proven 2.687 ms/layer): split-k GEMM,
// 16 warps; register gx prefetch; spill gbA/gbB; update sums + cell.
// ---------------------------------------------------------------------------
#define UPD_ITERS ((HH * 32 + RTHR - 1) / RTHR)   // 5

template <bool WRITE_SEQ>
__global__ void __launch_bounds__(RTHR, 1)
lstm_rec(const float* __restrict__ gx, const float* __restrict__ Whh,
         float* __restrict__ seq_out, float* __restrict__ fin_out)
{
    extern __shared__ float sm[];
    float* Ws  = sm;                  // [HH][GP]   weights, col = gcol(j)
    float* hb  = Ws + HH * GP;        // [HH][32]   h state
    float* gbA = hb + HH * 32;        // [GP][33]   gate spill, k-half 0
    float* gbB = gbA + GP * 33;       // [GP][33]   gate spill, k-half 1

    const int tid  = threadIdx.x;
    const int lane = tid & 31;
    const int w    = tid >> 5;          // 0..15
    const int wr   = w & 7;             // row-quad index
    const int kh   = w >> 3;            // k-half
    const int row0 = blockIdx.x * 32;

    for (int i = tid; i < HH * GP; i += RTHR) Ws[i] = 0.f;
    for (int i = tid; i < HH * 32; i += RTHR) hb[i] = 0.f;
    __syncthreads();

    for (int idx = tid; idx < 4 * HH * HH; idx += RTHR) {
        int j = idx / HH, k = idx - j * HH;
        Ws[k * GP + gcol(j)] = Whh[idx];
    }
    __syncthreads();

    float creg[UPD_ITERS];
#pragma unroll
    for (int i = 0; i < UPD_ITERS; i++) creg[i] = 0.f;

    // GEMM bases for this warp's k-half
    const float* Wl0 = Ws + lane + (kh ? 35 * GP : 0);
    const float* hr0 = hb + 4 * wr + (kh ? 35 * 32 : 0);
    float* gb = kh ? gbB : gbA;

    for (int t = 0; t < TT; t++) {
        // ---- prefetch this step's gx for the update pass (coalesced LDG)
        float cur[UPD_ITERS][4];
        {
            const float* gxt = gx + (size_t)t * GP * BB + row0;
#pragma unroll
            for (int i = 0; i < UPD_ITERS; i++) {
                int idx = tid + i * RTHR;
                if (idx < HH * 32) {
                    int n = idx >> 5, r = idx & 31;
#pragma unroll
                    for (int g = 0; g < 4; g++)
                        cur[i][g] = gxt[(size_t)(4 * n + g) * BB + r];
                }
            }
        }

        // ---- GEMM (35 k-iters): acc[2j+p] = row pair of col lane+32j
        u64 acc[18];
#pragma unroll
        for (int q = 0; q < 18; q++) acc[q] = 0ull;

#pragma unroll 5
        for (int k = 0; k < 35; k++) {
            ulonglong2 h2 =
                *reinterpret_cast<const ulonglong2*>(hr0 + k * 32);
            const float* Wk = Wl0 + k * GP;
#pragma unroll
            for (int j = 0; j < 9; j++) {
                u64 w2 = dup2(Wk[32 * j]);
                FMA2A(acc[2 * j],     w2, h2.x);
                FMA2A(acc[2 * j + 1], w2, h2.y);
            }
        }

        // ---- spill gates: gb[c][4wr+u], c = lane + 32j
#pragma unroll
        for (int j = 0; j < 9; j++) {
            int c = lane + 32 * j;
            float v0, v1, v2, v3;
            unpack2f(acc[2 * j],     v0, v1);
            unpack2f(acc[2 * j + 1], v2, v3);
            gb[c * 33 + 4 * wr + 0] = v0;
            gb[c * 33 + 4 * wr + 1] = v1;
            gb[c * 33 + 4 * wr + 2] = v2;
            gb[c * 33 + 4 * wr + 3] = v3;
        }
        __syncthreads();   // GEMM hb reads + both spills complete

        // ---- cell update: flat over (unit, row)
#pragma unroll
        for (int i = 0; i < UPD_ITERS; i++) {
            int idx = tid + i * RTHR;
            if (idx < HH * 32) {
                int n = idx >> 5, r = idx & 31;
                float gi = gbA[(4 * n + 0) * 33 + r] + gbB[(4 * n + 0) * 33 + r] + cur[i][0];
                float gf = gbA[(4 * n + 1) * 33 + r] + gbB[(4 * n + 1) * 33 + r] + cur[i][1];
                float gg = gbA[(4 * n + 2) * 33 + r] + gbB[(4 * n + 2) * 33 + r] + cur[i][2];
                float go = gbA[(4 * n + 3) * 33 + r] + gbB[(4 * n + 3) * 33 + r] + cur[i][3];
                float iv = sigm(gi);
                float fv = sigm(gf);
                float gv = tanh_(gg);
                float ov = sigm(go);
                float c = __fmaf_rn(fv, creg[i], iv * gv);
                creg[i] = c;
                float h = ov * tanh_(c);
                hb[n * 32 + r] = h;
                if (WRITE_SEQ)
                    seq_out[((size_t)t * HH + n) * BB + row0 + r] = h;
                if (!WRITE_SEQ && t == TT - 1)
                    fin_out[(size_t)n * BB + row0 + r] = h;
            }
        }
        __syncthreads();   // hb(t) ready, gb consumed, before next spill
    }
}

// head: out = sigmoid(relu(h1 @ W1.T + b1) @ W2.T + b2)
__global__ void __launch_bounds__(256)
head_kernel(const float* __restrict__ h1,
            const float* __restrict__ W1, const float* __restrict__ b1,
            const float* __restrict__ W2, const float* __restrict__ b2,
            float* __restrict__ out)
{
    __shared__ float sW1[50 * HH];
    __shared__ float sb1[50];
    __shared__ float sW2[50];
    __shared__ float sb2;
    for (int i = threadIdx.x; i < 50 * HH; i += 256) sW1[i] = W1[i];
    if (threadIdx.x < 50) {
        sb1[threadIdx.x] = b1[threadIdx.x];
        sW2[threadIdx.x] = W2[threadIdx.x];
    }
    if (threadIdx.x == 0) sb2 = b2[0];
    __syncthreads();

    int row = blockIdx.x * 256 + threadIdx.x;
    float h[HH];
#pragma unroll
    for (int n = 0; n < HH; n++) h[n] = h1[n * BB + row];

    float o = sb2;
    for (int s = 0; s < 50; s++) {
        float a = sb1[s];
#pragma unroll
        for (int n = 0; n < HH; n++) a += h[n] * sW1[s * HH + n];
        a = fmaxf(a, 0.f);
        o += a * sW2[s];
    }
    out[row] = sigm(o);
}

extern "C" void kernel_launch(void* const* d_in, const int* in_sizes, int n_in,
                              void* d_out, int out_size)
{
    int o = (n_in >= 14 && in_sizes[1] == 1) ? 2 : 1;
    const float* data_in = (const float*)d_in[0];
    const float* W_ih0 = (const float*)d_in[o + 0];
    const float* W_hh0 = (const float*)d_in[o + 1];
    const float* b_ih0 = (const float*)d_in[o + 2];
    const float* b_hh0 = (const float*)d_in[o + 3];
    const float* W_ih1 = (const float*)d_in[o + 4];
    const float* W_hh1 = (const float*)d_in[o + 5];
    const float* b_ih1 = (const float*)d_in[o + 6];
    const float* b_hh1 = (const float*)d_in[o + 7];
    const float* W1    = (const float*)d_in[o + 8];
    const float* b1    = (const float*)d_in[o + 9];
    const float* W2    = (const float*)d_in[o + 10];
    const float* b2    = (const float*)d_in[o + 11];

    float *gxp = nullptr, *h0p = nullptr, *h1p = nullptr;
    cudaGetSymbolAddress((void**)&gxp, g_gx);
    cudaGetSymbolAddress((void**)&h0p, g_h0);
    cudaGetSymbolAddress((void**)&h1p, g_h1);

    const int smx0 = ((DD + 1) * GP) * 4 + 2 * (128 * 68) * 4;   // ~145 KB
    const int smx1 = ((HH + 1) * GP) * 4 + 2 * (HH * 128) * 4;   // ~154 KB
    const int smr  = (HH * GP + HH * 32 + 2 * GP * 33) * 4;      // ~162 KB

    cudaFuncSetAttribute((const void*)gemm_x<DD, true>,
                         cudaFuncAttributeMaxDynamicSharedMemorySize, smx0);
    cudaFuncSetAttribute((const void*)gemm_x<HH, false>,
                         cudaFuncAttributeMaxDynamicSharedMemorySize, smx1);
    cudaFuncSetAttribute((const void*)lstm_rec<true>,
                         cudaFuncAttributeMaxDynamicSharedMemorySize, smr);
    cudaFuncSetAttribute((const void*)lstm_rec<false>,
                         cudaFuncAttributeMaxDynamicSharedMemorySize, smr);

    gemm_x<DD, true><<<NPERS, GTHR, smx0>>>(data_in, W_ih0, b_ih0, b_hh0, gxp);
    lstm_rec<true><<<RBLK, RTHR, smr>>>(gxp, W_hh0, h0p, nullptr);
    gemm_x<HH, false><<<NPERS, GTHR, smx1>>>(h0p, W_ih1, b_ih1, b_hh1, gxp);
    lstm_rec<false><<<RBLK, RTHR, smr>>>(gxp, W_hh1, nullptr, h1p);
    head_kernel<<<BB / 256, 256>>>(h1p, W1, b1, W2, b2, (float*)d_out);
}